// round 2
// baseline (speedup 1.0000x reference)
#include <cuda_runtime.h>
#include <cstdint>
#include <cstddef>

#define DEV __device__ __forceinline__

// ---------------- problem constants ----------------
static constexpr int BB = 32;
static constexpr int SEQ = 2048;
static constexpr int DD = 1024;    // K
static constexpr int SZ = 1024;    // SIZE

static constexpr int M_TILE = 128;
static constexpr int N_TILE = 256;
static constexpr int PASSES = SZ / N_TILE;   // 4
static constexpr int K_CHUNK = 32;
static constexpr int NCHUNK = DD / K_CHUNK;  // 32
static constexpr int THREADS = 256;
static constexpr int KPAD = 36;              // floats per smem row (144 B)

// smem layout in floats
static constexpr int S_A0 = 0;
static constexpr int A_FLOATS = M_TILE * KPAD;        // 4608
static constexpr int S_A1 = S_A0 + A_FLOATS;
static constexpr int S_B0 = S_A1 + A_FLOATS;          // 9216
static constexpr int B_FLOATS = N_TILE * KPAD;        // 9216
static constexpr int S_B1 = S_B0 + B_FLOATS;
static constexpr int S_T2 = S_B1 + B_FLOATS;          // 27648
static constexpr int S_V  = S_T2 + SZ;
static constexpr int S_PART = S_V + SZ;
static constexpr int SMEM_FLOATS = S_PART + M_TILE;
static constexpr int SMEM_BYTES = SMEM_FLOATS * 4;    // ~119 KB

// scratch: tf32-rounded copies + term2
__device__ float g_Xr[(size_t)BB * SEQ * DD];   // 256 MB
__device__ float g_WOr[(size_t)SZ * DD];        // 4 MB
__device__ float g_term2[BB * SZ];

// ---------------- helpers ----------------
DEV uint32_t smem_u32(const void* p) {
    uint32_t a;
    asm("{ .reg .u64 t; cvta.to.shared.u64 t, %1; cvt.u32.u64 %0, t; }" : "=r"(a) : "l"(p));
    return a;
}
DEV void cp16(uint32_t s, const void* g) {
    asm volatile("cp.async.cg.shared.global [%0], [%1], 16;" :: "r"(s), "l"(g));
}
DEV void cp_commit() { asm volatile("cp.async.commit_group;" ::: "memory"); }
template <int N> DEV void cp_wait() { asm volatile("cp.async.wait_group %0;" :: "n"(N) : "memory"); }

DEV float tanh_fast(float x) {
    float y;
    asm("tanh.approx.f32 %0, %1;" : "=f"(y) : "f"(x));
    return y;
}
DEV uint32_t rna_tf32(uint32_t b) {
    return (b + 0xFFFu + ((b >> 13) & 1u)) & 0xFFFFE000u;
}

DEV void mma_tf32(float* d, const uint32_t* a, const uint32_t* b) {
    asm volatile(
        "mma.sync.aligned.m16n8k8.row.col.f32.tf32.tf32.f32 "
        "{%0,%1,%2,%3}, {%4,%5,%6,%7}, {%8,%9}, {%0,%1,%2,%3};"
        : "+f"(d[0]), "+f"(d[1]), "+f"(d[2]), "+f"(d[3])
        : "r"(a[0]), "r"(a[1]), "r"(a[2]), "r"(a[3]), "r"(b[0]), "r"(b[1]));
}

// stage [rows x 32] fp32 tile (gmem row stride 1024 floats) into smem rows of KPAD floats
DEV void stage(float* sdst, const float* gsrc, int rows, int tid) {
    const uint32_t sb = smem_u32(sdst);
    const int total = rows * 8;
    for (int gidx = tid; gidx < total; gidx += THREADS) {
        const int r = gidx >> 3, c = gidx & 7;
        cp16(sb + (uint32_t)(r * KPAD + c * 4) * 4u, gsrc + (size_t)r * DD + c * 4);
    }
}

// ---------------- prepass: tf32-rna rounding ----------------
__global__ void round_kernel(const float* __restrict__ src, float* __restrict__ dst, int n4) {
    int i = blockIdx.x * blockDim.x + threadIdx.x;
    if (i >= n4) return;
    uint4 u = ((const uint4*)src)[i];
    u.x = rna_tf32(u.x); u.y = rna_tf32(u.y); u.z = rna_tf32(u.z); u.w = rna_tf32(u.w);
    ((uint4*)dst)[i] = u;
}

// ---------------- term2 = WG @ g  (exact fp32 SIMT) ----------------
__global__ void term2_kernel(const float* __restrict__ WG, const float* __restrict__ g) {
    __shared__ float4 gs[256];
    const int b = blockIdx.y;
    gs[threadIdx.x] = ((const float4*)(g + (size_t)b * DD))[threadIdx.x];
    __syncthreads();
    const int w = threadIdx.x >> 5, l = threadIdx.x & 31;
    const int n = blockIdx.x * 8 + w;
    const float4* wg4 = (const float4*)(WG + (size_t)n * DD);
    float s = 0.f;
#pragma unroll
    for (int i = 0; i < 8; i++) {
        float4 a = wg4[l + 32 * i];
        float4 gg = gs[l + 32 * i];
        s += a.x * gg.x + a.y * gg.y + a.z * gg.z + a.w * gg.w;
    }
#pragma unroll
    for (int o = 16; o; o >>= 1) s += __shfl_xor_sync(0xFFFFFFFFu, s, o);
    if (l == 0) g_term2[b * SZ + n] = s;
}

// ---------------- fused GEMM(tf32 mma.sync) + tanh + v-dot ----------------
__global__ __launch_bounds__(THREADS, 1)
void fused_kernel(const float* __restrict__ v, float* __restrict__ out) {
    extern __shared__ float smem[];
    const int tid = threadIdx.x;
    const int lane = tid & 31, wid = tid >> 5;
    const int wm = wid >> 2, wn = wid & 3;      // 2 x 4 warp grid
    const int m0 = blockIdx.x * M_TILE;
    const int bidx = m0 >> 11;                  // batch index (2048 rows per batch)

    float* t2s = smem + S_T2;
    float* vs  = smem + S_V;
    float* part = smem + S_PART;

    for (int i = tid; i < SZ; i += THREADS) {
        t2s[i] = g_term2[bidx * SZ + i];
        vs[i] = v[i];
    }
    for (int i = tid; i < M_TILE; i += THREADS) part[i] = 0.f;
    __syncthreads();

    const float* Xbase = g_Xr + (size_t)m0 * DD;

    float racc[8];
#pragma unroll
    for (int j = 0; j < 8; j++) racc[j] = 0.f;

    const int ar = lane >> 2;   // group id
    const int ak = lane & 3;    // thread-in-group

    for (int p = 0; p < PASSES; p++) {
        const float* Wbase = g_WOr + (size_t)p * N_TILE * DD;

        float acc[4][8][4];
#pragma unroll
        for (int mt = 0; mt < 4; mt++)
#pragma unroll
            for (int nt = 0; nt < 8; nt++)
#pragma unroll
                for (int q = 0; q < 4; q++) acc[mt][nt][q] = 0.f;

        // prologue: chunk 0 -> buffer 0
        stage(smem + S_A0, Xbase, M_TILE, tid);
        stage(smem + S_B0, Wbase, N_TILE, tid);
        cp_commit();

#pragma unroll 1
        for (int c = 0; c < NCHUNK; c++) {
            if (c + 1 < NCHUNK) {
                float* an = smem + (((c + 1) & 1) ? S_A1 : S_A0);
                float* bn = smem + (((c + 1) & 1) ? S_B1 : S_B0);
                stage(an, Xbase + (c + 1) * K_CHUNK, M_TILE, tid);
                stage(bn, Wbase + (c + 1) * K_CHUNK, N_TILE, tid);
                cp_commit();
                cp_wait<1>();
            } else {
                cp_wait<0>();
            }
            __syncthreads();

            const uint32_t* As = (const uint32_t*)(smem + ((c & 1) ? S_A1 : S_A0));
            const uint32_t* Bs = (const uint32_t*)(smem + ((c & 1) ? S_B1 : S_B0));

#pragma unroll
            for (int k8 = 0; k8 < 4; k8++) {
                const int ko = k8 * 8;
                uint32_t a[4][4], b[8][2];
#pragma unroll
                for (int mt = 0; mt < 4; mt++) {
                    const int r0 = (wm * 64 + mt * 16 + ar) * KPAD + ko + ak;
                    a[mt][0] = As[r0];
                    a[mt][1] = As[r0 + 8 * KPAD];
                    a[mt][2] = As[r0 + 4];
                    a[mt][3] = As[r0 + 8 * KPAD + 4];
                }
#pragma unroll
                for (int nt = 0; nt < 8; nt++) {
                    const int nb = (wn * 64 + nt * 8 + ar) * KPAD + ko + ak;
                    b[nt][0] = Bs[nb];
                    b[nt][1] = Bs[nb + 4];
                }
#pragma unroll
                for (int mt = 0; mt < 4; mt++)
#pragma unroll
                    for (int nt = 0; nt < 8; nt++)
                        mma_tf32(acc[mt][nt], a[mt], b[nt]);
            }
            __syncthreads();
        }

        // ---- epilogue for this N pass: acc -> tanh -> v-dot row partials ----
#pragma unroll
        for (int mt = 0; mt < 4; mt++) {
#pragma unroll
            for (int nt = 0; nt < 8; nt++) {
                const int gn = p * N_TILE + wn * 64 + nt * 8 + 2 * ak;
                const float v0 = vs[gn], v1 = vs[gn + 1];
                const float t20 = t2s[gn], t21 = t2s[gn + 1];
                racc[mt * 2] += v0 * tanh_fast(acc[mt][nt][0] + t20)
                              + v1 * tanh_fast(acc[mt][nt][1] + t21);
                racc[mt * 2 + 1] += v0 * tanh_fast(acc[mt][nt][2] + t20)
                                  + v1 * tanh_fast(acc[mt][nt][3] + t21);
            }
        }
    }

    // reduce over the 4 lanes of each column group
#pragma unroll
    for (int j = 0; j < 8; j++) {
        racc[j] += __shfl_xor_sync(0xFFFFFFFFu, racc[j], 1);
        racc[j] += __shfl_xor_sync(0xFFFFFFFFu, racc[j], 2);
    }
    if (ak == 0) {
#pragma unroll
        for (int j = 0; j < 8; j++) {
            const int row = wm * 64 + (j >> 1) * 16 + ar + (j & 1) * 8;
            atomicAdd(&part[row], racc[j]);
        }
    }
    __syncthreads();
    if (tid < M_TILE) out[m0 + tid] = part[tid];
}

// ---------------- launch ----------------
extern "C" void kernel_launch(void* const* d_in, const int* in_sizes, int n_in,
                              void* d_out, int out_size) {
    const float* X  = (const float*)d_in[0];   // inputs [B,S,D]
    const float* g  = (const float*)d_in[1];   // g [B,D]
    const float* WO = (const float*)d_in[2];   // WO [SIZE,D]
    const float* WG = (const float*)d_in[3];   // WG [SIZE,D]
    const float* v  = (const float*)d_in[4];   // v [1,SIZE]
    float* out = (float*)d_out;

    float* Xr;  cudaGetSymbolAddress((void**)&Xr,  g_Xr);
    float* WOr; cudaGetSymbolAddress((void**)&WOr, g_WOr);

    cudaFuncSetAttribute(fused_kernel, cudaFuncAttributeMaxDynamicSharedMemorySize, SMEM_BYTES);

    const int nX4 = BB * SEQ * DD / 4;
    round_kernel<<<nX4 / 256, 256>>>(X, Xr, nX4);
    const int nW4 = SZ * DD / 4;
    round_kernel<<<nW4 / 256, 256>>>(WO, WOr, nW4);
    term2_kernel<<<dim3(SZ / 8, BB), 256>>>(WG, g);

    fused_kernel<<<(BB * SEQ) / M_TILE, THREADS, SMEM_BYTES>>>(v, out);
}